// round 10
// baseline (speedup 1.0000x reference)
#include <cuda_runtime.h>
#include <math.h>
#include <stdint.h>

#define N_NODES 100000
#define N_EDGES 200000
#define NNZ_    1600000
#define INC 128
#define OUTC 128
#define STAR_ 64
#define KTOT 192

typedef unsigned long long u64;

// ---------------- device scratch (allocation-free) ----------------
__device__ float g_Xfeat[(size_t)N_NODES * OUTC];   // 51.2 MB
__device__ float g_w[N_NODES];                      // exp(leaky(score)) per node
__device__ float g_Yv2e[(size_t)N_EDGES * OUTC];    // 102.4 MB (elu'd rows)

// CSR by edge (payload = V) / by node (payload = E)
__device__ int g_histE[N_EDGES];
__device__ int g_baseE[N_EDGES];
__device__ int g_curE[N_EDGES];
__device__ int g_csrE_v[NNZ_];
__device__ int g_histV[N_NODES];
__device__ int g_baseV[N_NODES];
__device__ int g_curV[N_NODES];
__device__ int g_csrV_e[NNZ_];
__device__ int g_alloc_ctr[2];

// ---------------- helpers ----------------
__device__ __forceinline__ float elu1(float x) {
    return x > 0.f ? x : expm1f(x);
}
// packed f32x2 FMA (Blackwell FFMA2 path via PTX)
__device__ __forceinline__ u64 pack2(float v) {
    u64 r; asm("mov.b64 %0, {%1, %1};" : "=l"(r) : "f"(v)); return r;
}
__device__ __forceinline__ void fma2(u64& d, u64 a, u64 b) {
    asm("fma.rn.f32x2 %0, %1, %2, %0;" : "+l"(d) : "l"(a), "l"(b));
}
__device__ __forceinline__ float2 unpack2(u64 v) {
    float2 r; asm("mov.b64 {%0, %1}, %2;" : "=f"(r.x), "=f"(r.y) : "l"(v)); return r;
}

// ---------------- Kernel 1: X_init = X@Wx+bx ; X_feat = X@Wv+bv ; w = exp(leaky(X_feat@a)) ----------------
// 64 rows x 128 cols per block; W staged in 2 k-chunks of 64 -> 102 KB smem -> 2 CTAs/SM.
__global__ __launch_bounds__(256, 2) void gemm_x_kernel(
    const float* __restrict__ X, const float* __restrict__ Wx, const float* __restrict__ bx,
    const float* __restrict__ Wv, const float* __restrict__ bv, const float* __restrict__ a_vec,
    float* __restrict__ Xinit)
{
    extern __shared__ float sm[];
    float* sXT = sm;                 // 128*72  (k-major, transposed X tile)
    float* sWx = sm + 128 * 72;      // 64*132  (one k-chunk)
    float* sWv = sWx + 64 * 132;     // 64*132

    const int tx = threadIdx.x;
    const int n0 = blockIdx.x * 64;

    #pragma unroll
    for (int it = 0; it < 8; it++) {
        int idx = tx + it * 256;
        int row = idx >> 5;
        int kq  = idx & 31;
        int n = n0 + row;
        float4 v = make_float4(0.f, 0.f, 0.f, 0.f);
        if (n < N_NODES) v = *(const float4*)&X[(size_t)n * INC + kq * 4];
        sXT[(kq * 4 + 0) * 72 + row] = v.x;
        sXT[(kq * 4 + 1) * 72 + row] = v.y;
        sXT[(kq * 4 + 2) * 72 + row] = v.z;
        sXT[(kq * 4 + 3) * 72 + row] = v.w;
    }

    const int c0 = (tx & 31) * 4;
    const int r0 = (tx >> 5) * 8;

    u64 ax0[8], ax1[8], av0[8], av1[8];
    #pragma unroll
    for (int i = 0; i < 8; i++) { ax0[i] = 0ull; ax1[i] = 0ull; av0[i] = 0ull; av1[i] = 0ull; }

    #pragma unroll
    for (int c = 0; c < 2; c++) {
        #pragma unroll
        for (int it = 0; it < 8; it++) {
            int idx = tx + it * 256;          // 64 rows * 32 float4
            int k  = idx >> 5;
            int cq = idx & 31;
            *(float4*)&sWx[k * 132 + cq * 4] = *(const float4*)&Wx[(c * 64 + k) * OUTC + cq * 4];
            *(float4*)&sWv[k * 132 + cq * 4] = *(const float4*)&Wv[(c * 64 + k) * OUTC + cq * 4];
        }
        __syncthreads();

        #pragma unroll 4
        for (int kk = 0; kk < 64; kk++) {
            int k = c * 64 + kk;
            ulonglong2 wx = *(ulonglong2*)&sWx[kk * 132 + c0];
            ulonglong2 wv = *(ulonglong2*)&sWv[kk * 132 + c0];
            float4 xa = *(float4*)&sXT[k * 72 + r0];
            float4 xb = *(float4*)&sXT[k * 72 + r0 + 4];
            float xs[8] = {xa.x, xa.y, xa.z, xa.w, xb.x, xb.y, xb.z, xb.w};
            #pragma unroll
            for (int i = 0; i < 8; i++) {
                u64 xx = pack2(xs[i]);
                fma2(ax0[i], xx, wx.x); fma2(ax1[i], xx, wx.y);
                fma2(av0[i], xx, wv.x); fma2(av1[i], xx, wv.y);
            }
        }
        __syncthreads();
    }

    float4 bx4 = *(const float4*)&bx[c0];
    float4 bv4 = *(const float4*)&bv[c0];
    float4 aa4 = *(const float4*)&a_vec[c0];
    const int lane = tx & 31;
    #pragma unroll
    for (int i = 0; i < 8; i++) {
        int n = n0 + r0 + i;
        if (n < N_NODES) {   // warp-uniform guard
            float2 x01 = unpack2(ax0[i]), x23 = unpack2(ax1[i]);
            float4 o = make_float4(x01.x + bx4.x, x01.y + bx4.y, x23.x + bx4.z, x23.y + bx4.w);
            *(float4*)&Xinit[(size_t)n * OUTC + c0] = o;
            float2 v01 = unpack2(av0[i]), v23 = unpack2(av1[i]);
            float4 f = make_float4(v01.x + bv4.x, v01.y + bv4.y, v23.x + bv4.z, v23.y + bv4.w);
            *(float4*)&g_Xfeat[(size_t)n * OUTC + c0] = f;
            float part = f.x * aa4.x + f.y * aa4.y + f.z * aa4.z + f.w * aa4.w;
            #pragma unroll
            for (int off = 16; off; off >>= 1) part += __shfl_down_sync(0xffffffffu, part, off);
            if (lane == 0) {
                float s = part > 0.f ? part : 0.2f * part;
                g_w[n] = expf(s);
            }
        }
    }
}

// ---------------- histogram: deg per edge + deg per node ----------------
__global__ __launch_bounds__(256) void hist_kernel(const int* __restrict__ V, const int* __restrict__ E)
{
    int i = blockIdx.x * 256 + threadIdx.x;     // 6250*256 = NNZ exact
    atomicAdd(&g_histE[__ldg(&E[i])], 1);
    atomicAdd(&g_histV[__ldg(&V[i])], 1);
}

// ---------------- segment-base allocation ----------------
__global__ __launch_bounds__(256) void alloc_kernel(const int* __restrict__ hist,
        int* __restrict__ base, int* __restrict__ cur, int len, int ctr_idx)
{
    __shared__ int s_warp[8];
    __shared__ int s_base;
    const int t = threadIdx.x;
    const int i = blockIdx.x * 256 + t;
    const int lane = t & 31, wid = t >> 5;
    int v = (i < len) ? hist[i] : 0;
    int x = v;
    #pragma unroll
    for (int off = 1; off < 32; off <<= 1) {
        int y = __shfl_up_sync(0xffffffffu, x, off);
        if (lane >= off) x += y;
    }
    if (lane == 31) s_warp[wid] = x;
    __syncthreads();
    if (wid == 0) {
        int orig = (lane < 8) ? s_warp[lane] : 0;
        int s = orig;
        #pragma unroll
        for (int off = 1; off < 8; off <<= 1) {
            int y = __shfl_up_sync(0xffffffffu, s, off);
            if (lane >= off) s += y;
        }
        if (lane == 7) s_base = atomicAdd(&g_alloc_ctr[ctr_idx], s);
        if (lane < 8) s_warp[lane] = s - orig;
    }
    __syncthreads();
    if (i < len) {
        int excl = (x - v) + s_warp[wid] + s_base;
        base[i] = excl;
        cur[i]  = excl;
    }
}

// ---------------- scatter nnz into both CSRs ----------------
__global__ __launch_bounds__(256) void scatter_kernel(const int* __restrict__ V, const int* __restrict__ E)
{
    int i = blockIdx.x * 256 + threadIdx.x;     // NNZ exact
    int v = __ldg(&V[i]);
    int e = __ldg(&E[i]);
    int pE = atomicAdd(&g_curE[e], 1);
    g_csrE_v[pE] = v;
    int pV = atomicAdd(&g_curV[v], 1);
    g_csrV_e[pV] = e;
}

// ---------------- edge aggregation: Yv2e[e] = elu( sum w_v*Xfeat[v] / sum w_v ) ----------------
__global__ __launch_bounds__(256) void edge_agg_kernel()
{
    const int e = blockIdx.x * 8 + (threadIdx.x >> 5);   // 25000*8 = 200000
    const int lane = threadIdx.x & 31;
    const int base = g_baseE[e];
    const int deg  = g_histE[e];
    float4 acc = make_float4(0.f, 0.f, 0.f, 0.f);
    float denom = 0.f;
    int vcur = (deg > 0) ? __ldg(&g_csrE_v[base]) : 0;
    for (int j = 0; j < deg; j++) {
        int v = vcur;
        if (j + 1 < deg) vcur = __ldg(&g_csrE_v[base + j + 1]);   // prefetch next index
        float wv = __ldg(&g_w[v]);
        float4 xf = *(const float4*)&g_Xfeat[(size_t)v * OUTC + lane * 4];
        denom += wv;
        acc.x += wv * xf.x; acc.y += wv * xf.y; acc.z += wv * xf.z; acc.w += wv * xf.w;
    }
    float inv = (deg > 0) ? (1.f / denom) : 0.f;
    float4 o;
    o.x = elu1(acc.x * inv); o.y = elu1(acc.y * inv);
    o.z = elu1(acc.z * inv); o.w = elu1(acc.w * inv);
    *(float4*)&g_Yv2e[(size_t)e * OUTC + lane * 4] = o;
}

// ---------------- fused node aggregation + GEMM: out = X_init + (deg>0 ? elu(mean@Wt + bt) : 0) ----------------
// Phase 1: each warp gathers+means 8 node rows of [Yv2e, S] straight into the smem GEMM tile.
// Phase 2: 64x128 FFMA2 GEMM, K=192, Wt staged in 6 chunks of 32 rows.
// smem: sM[64][200] row-major message tile (51.2 KB) + sW[32][132] (16.9 KB) + sDeg[64]
#define SMROW 200
__global__ __launch_bounds__(256, 2) void node_gemm_fused_kernel(
    const float* __restrict__ S, const float* __restrict__ Wt, const float* __restrict__ bt,
    float* __restrict__ out)
{
    extern __shared__ float sm[];
    float* sM = sm;                        // 64*200
    float* sW = sm + 64 * SMROW;           // 32*132
    int*  sDeg = (int*)(sW + 32 * 132);    // 64

    const int tx = threadIdx.x;
    const int wid = tx >> 5, lane = tx & 31;
    const int n0 = blockIdx.x * 64;

    // ---- phase 1: gather means for rows wid*8 .. wid*8+7 ----
    #pragma unroll 1
    for (int m = 0; m < 8; m++) {
        int row = wid * 8 + m;
        int n = n0 + row;
        float4 accY = make_float4(0.f, 0.f, 0.f, 0.f);
        float2 accS = make_float2(0.f, 0.f);
        int deg = 0;
        if (n < N_NODES) {
            int base = g_baseV[n];
            deg = g_histV[n];
            int ecur = (deg > 0) ? __ldg(&g_csrV_e[base]) : 0;
            for (int j = 0; j < deg; j++) {
                int e = ecur;
                if (j + 1 < deg) ecur = __ldg(&g_csrV_e[base + j + 1]);   // prefetch next index
                float4 y = *(const float4*)&g_Yv2e[(size_t)e * OUTC + lane * 4];
                accY.x += y.x; accY.y += y.y; accY.z += y.z; accY.w += y.w;
                float2 s2 = *(const float2*)&S[(size_t)e * STAR_ + lane * 2];
                accS.x += s2.x; accS.y += s2.y;
            }
        }
        float inv = 1.f / fmaxf((float)deg, 1.f);
        accY.x *= inv; accY.y *= inv; accY.z *= inv; accY.w *= inv;
        accS.x *= inv; accS.y *= inv;
        *(float4*)&sM[row * SMROW + lane * 4] = accY;
        *(float2*)&sM[row * SMROW + OUTC + lane * 2] = accS;
        if (lane == 0) sDeg[row] = deg;
    }
    __syncthreads();

    // ---- phase 2: GEMM ----
    const int c0 = (tx & 31) * 4;
    const int r0 = (tx >> 5) * 8;

    u64 a0[8], a1[8];
    #pragma unroll
    for (int i = 0; i < 8; i++) { a0[i] = 0ull; a1[i] = 0ull; }

    #pragma unroll 1
    for (int c = 0; c < 6; c++) {
        #pragma unroll
        for (int it = 0; it < 4; it++) {
            int idx = tx + it * 256;      // 32 rows * 32 float4
            int k  = idx >> 5;
            int cq = idx & 31;
            *(float4*)&sW[k * 132 + cq * 4] = *(const float4*)&Wt[(c * 32 + k) * OUTC + cq * 4];
        }
        __syncthreads();

        #pragma unroll 4
        for (int kk = 0; kk < 32; kk++) {
            int k = c * 32 + kk;
            ulonglong2 w2 = *(ulonglong2*)&sW[kk * 132 + c0];
            #pragma unroll
            for (int i = 0; i < 8; i++) {
                u64 xx = pack2(sM[(r0 + i) * SMROW + k]);   // warp-broadcast LDS
                fma2(a0[i], xx, w2.x); fma2(a1[i], xx, w2.y);
            }
        }
        __syncthreads();
    }

    float4 bt4 = *(const float4*)&bt[c0];
    #pragma unroll
    for (int i = 0; i < 8; i++) {
        int n = n0 + r0 + i;
        if (n < N_NODES) {
            size_t oidx = (size_t)n * OUTC + c0;
            float4 o = *(const float4*)&out[oidx];           // X_init
            if (sDeg[r0 + i] > 0) {                          // isolated node -> elu(0)=0
                float2 p01 = unpack2(a0[i]), p23 = unpack2(a1[i]);
                o.x += elu1(p01.x + bt4.x);
                o.y += elu1(p01.y + bt4.y);
                o.z += elu1(p23.x + bt4.z);
                o.w += elu1(p23.y + bt4.w);
            }
            *(float4*)&out[oidx] = o;
        }
    }
}

// ---------------- launch ----------------
extern "C" void kernel_launch(void* const* d_in, const int* in_sizes, int n_in,
                              void* d_out, int out_size)
{
    const float* X  = (const float*)d_in[0];
    const int*   V  = (const int*)d_in[1];
    const int*   E  = (const int*)d_in[2];
    const float* S  = (const float*)d_in[3];
    const float* Wx = (const float*)d_in[4];
    const float* bx = (const float*)d_in[5];
    const float* Wv = (const float*)d_in[6];
    const float* bv = (const float*)d_in[7];
    const float* a  = (const float*)d_in[8];
    const float* Wt = (const float*)d_in[9];
    const float* bt = (const float*)d_in[10];
    float* out = (float*)d_out;

    void *p_histE, *p_histV, *p_ctr, *p_baseE, *p_curE, *p_baseV, *p_curV;
    cudaGetSymbolAddress(&p_histE, g_histE);
    cudaGetSymbolAddress(&p_histV, g_histV);
    cudaGetSymbolAddress(&p_ctr,   g_alloc_ctr);
    cudaGetSymbolAddress(&p_baseE, g_baseE);
    cudaGetSymbolAddress(&p_curE,  g_curE);
    cudaGetSymbolAddress(&p_baseV, g_baseV);
    cudaGetSymbolAddress(&p_curV,  g_curV);
    cudaMemsetAsync(p_histE, 0, N_EDGES * sizeof(int));
    cudaMemsetAsync(p_histV, 0, N_NODES * sizeof(int));
    cudaMemsetAsync(p_ctr,   0, 2 * sizeof(int));

    const int smem1 = (128 * 72 + 2 * 64 * 132) * (int)sizeof(float);           // 104448
    const int smem2 = (64 * SMROW + 32 * 132) * (int)sizeof(float) + 64 * 4;    // 68352
    cudaFuncSetAttribute(gemm_x_kernel,          cudaFuncAttributeMaxDynamicSharedMemorySize, smem1);
    cudaFuncSetAttribute(node_gemm_fused_kernel, cudaFuncAttributeMaxDynamicSharedMemorySize, smem2);

    hist_kernel<<<6250, 256>>>(V, E);
    gemm_x_kernel<<<1563, 256, smem1>>>(X, Wx, bx, Wv, bv, a, out);
    alloc_kernel<<<782, 256>>>((const int*)p_histE, (int*)p_baseE, (int*)p_curE, N_EDGES, 0);
    alloc_kernel<<<391, 256>>>((const int*)p_histV, (int*)p_baseV, (int*)p_curV, N_NODES, 1);
    scatter_kernel<<<6250, 256>>>(V, E);
    edge_agg_kernel<<<25000, 256>>>();
    node_gemm_fused_kernel<<<1563, 256, smem2>>>(S, Wt, bt, out);
}

// round 11
// speedup vs baseline: 1.0450x; 1.0450x over previous
#include <cuda_runtime.h>
#include <cuda_fp16.h>
#include <math.h>
#include <stdint.h>

#define N_NODES 100000
#define N_EDGES 200000
#define NNZ_    1600000
#define INC 128
#define OUTC 128
#define STAR_ 64
#define KTOT 192

typedef unsigned long long u64;

// ---------------- device scratch (allocation-free) ----------------
__device__ float g_Xfeat[(size_t)N_NODES * OUTC];       // 51.2 MB
__device__ float g_w[N_NODES];                          // exp(leaky(score)) per node
__device__ __half2 g_Yv2e[(size_t)N_EDGES * (OUTC/2)];  // 51.2 MB (elu'd rows, fp16)

// zero region: [histE | histV | alloc_ctr(2)]  -> single memset
__device__ int g_zero[N_EDGES + N_NODES + 2];
__device__ int g_baseE[N_EDGES];
__device__ int g_curE[N_EDGES];
__device__ int g_csrE_v[NNZ_];
__device__ int g_baseV[N_NODES];
__device__ int g_curV[N_NODES];
__device__ int g_csrV_e[NNZ_];

// ---------------- helpers ----------------
__device__ __forceinline__ float elu1(float x) {
    return x > 0.f ? x : expm1f(x);
}
// packed f32x2 FMA (Blackwell FFMA2 path via PTX)
__device__ __forceinline__ u64 pack2(float v) {
    u64 r; asm("mov.b64 %0, {%1, %1};" : "=l"(r) : "f"(v)); return r;
}
__device__ __forceinline__ void fma2(u64& d, u64 a, u64 b) {
    asm("fma.rn.f32x2 %0, %1, %2, %0;" : "+l"(d) : "l"(a), "l"(b));
}
__device__ __forceinline__ float2 unpack2(u64 v) {
    float2 r; asm("mov.b64 {%0, %1}, %2;" : "=f"(r.x), "=f"(r.y) : "l"(v)); return r;
}

// ---------------- Kernel 1: X_init = X@Wx+bx ; X_feat = X@Wv+bv ; w = exp(leaky(X_feat@a)) ----------------
// 64 rows x 128 cols per block; W staged in 2 k-chunks of 64 -> 102 KB smem -> 2 CTAs/SM.
__global__ __launch_bounds__(256, 2) void gemm_x_kernel(
    const float* __restrict__ X, const float* __restrict__ Wx, const float* __restrict__ bx,
    const float* __restrict__ Wv, const float* __restrict__ bv, const float* __restrict__ a_vec,
    float* __restrict__ Xinit)
{
    extern __shared__ float sm[];
    float* sXT = sm;                 // 128*72  (k-major, transposed X tile)
    float* sWx = sm + 128 * 72;      // 64*132  (one k-chunk)
    float* sWv = sWx + 64 * 132;     // 64*132

    const int tx = threadIdx.x;
    const int n0 = blockIdx.x * 64;

    #pragma unroll
    for (int it = 0; it < 8; it++) {
        int idx = tx + it * 256;
        int row = idx >> 5;
        int kq  = idx & 31;
        int n = n0 + row;
        float4 v = make_float4(0.f, 0.f, 0.f, 0.f);
        if (n < N_NODES) v = *(const float4*)&X[(size_t)n * INC + kq * 4];
        sXT[(kq * 4 + 0) * 72 + row] = v.x;
        sXT[(kq * 4 + 1) * 72 + row] = v.y;
        sXT[(kq * 4 + 2) * 72 + row] = v.z;
        sXT[(kq * 4 + 3) * 72 + row] = v.w;
    }

    const int c0 = (tx & 31) * 4;
    const int r0 = (tx >> 5) * 8;

    u64 ax0[8], ax1[8], av0[8], av1[8];
    #pragma unroll
    for (int i = 0; i < 8; i++) { ax0[i] = 0ull; ax1[i] = 0ull; av0[i] = 0ull; av1[i] = 0ull; }

    #pragma unroll
    for (int c = 0; c < 2; c++) {
        #pragma unroll
        for (int it = 0; it < 8; it++) {
            int idx = tx + it * 256;          // 64 rows * 32 float4
            int k  = idx >> 5;
            int cq = idx & 31;
            *(float4*)&sWx[k * 132 + cq * 4] = *(const float4*)&Wx[(c * 64 + k) * OUTC + cq * 4];
            *(float4*)&sWv[k * 132 + cq * 4] = *(const float4*)&Wv[(c * 64 + k) * OUTC + cq * 4];
        }
        __syncthreads();

        #pragma unroll 4
        for (int kk = 0; kk < 64; kk++) {
            int k = c * 64 + kk;
            ulonglong2 wx = *(ulonglong2*)&sWx[kk * 132 + c0];
            ulonglong2 wv = *(ulonglong2*)&sWv[kk * 132 + c0];
            float4 xa = *(float4*)&sXT[k * 72 + r0];
            float4 xb = *(float4*)&sXT[k * 72 + r0 + 4];
            float xs[8] = {xa.x, xa.y, xa.z, xa.w, xb.x, xb.y, xb.z, xb.w};
            #pragma unroll
            for (int i = 0; i < 8; i++) {
                u64 xx = pack2(xs[i]);
                fma2(ax0[i], xx, wx.x); fma2(ax1[i], xx, wx.y);
                fma2(av0[i], xx, wv.x); fma2(av1[i], xx, wv.y);
            }
        }
        __syncthreads();
    }

    float4 bx4 = *(const float4*)&bx[c0];
    float4 bv4 = *(const float4*)&bv[c0];
    float4 aa4 = *(const float4*)&a_vec[c0];
    const int lane = tx & 31;
    #pragma unroll
    for (int i = 0; i < 8; i++) {
        int n = n0 + r0 + i;
        if (n < N_NODES) {   // warp-uniform guard
            float2 x01 = unpack2(ax0[i]), x23 = unpack2(ax1[i]);
            float4 o = make_float4(x01.x + bx4.x, x01.y + bx4.y, x23.x + bx4.z, x23.y + bx4.w);
            *(float4*)&Xinit[(size_t)n * OUTC + c0] = o;
            float2 v01 = unpack2(av0[i]), v23 = unpack2(av1[i]);
            float4 f = make_float4(v01.x + bv4.x, v01.y + bv4.y, v23.x + bv4.z, v23.y + bv4.w);
            *(float4*)&g_Xfeat[(size_t)n * OUTC + c0] = f;
            float part = f.x * aa4.x + f.y * aa4.y + f.z * aa4.z + f.w * aa4.w;
            #pragma unroll
            for (int off = 16; off; off >>= 1) part += __shfl_down_sync(0xffffffffu, part, off);
            if (lane == 0) {
                float s = part > 0.f ? part : 0.2f * part;
                g_w[n] = expf(s);
            }
        }
    }
}

// ---------------- histogram: deg per edge + deg per node (into zero region) ----------------
__global__ __launch_bounds__(256) void hist_kernel(const int* __restrict__ V, const int* __restrict__ E)
{
    int i = blockIdx.x * 256 + threadIdx.x;     // 6250*256 = NNZ exact
    atomicAdd(&g_zero[__ldg(&E[i])], 1);
    atomicAdd(&g_zero[N_EDGES + __ldg(&V[i])], 1);
}

// ---------------- segment-base allocation: edges (blocks 0..781) + nodes (blocks 782..1172) ----------------
__global__ __launch_bounds__(256) void alloc_kernel()
{
    __shared__ int s_warp[8];
    __shared__ int s_base;
    const int t = threadIdx.x;
    const bool isE = blockIdx.x < 782;
    const int i = (isE ? blockIdx.x : (blockIdx.x - 782)) * 256 + t;
    const int len = isE ? N_EDGES : N_NODES;
    const int* hist = isE ? g_zero : (g_zero + N_EDGES);
    int* base = isE ? g_baseE : g_baseV;
    int* cur  = isE ? g_curE  : g_curV;
    int* ctr  = &g_zero[N_EDGES + N_NODES + (isE ? 0 : 1)];

    const int lane = t & 31, wid = t >> 5;
    int v = (i < len) ? hist[i] : 0;
    int x = v;
    #pragma unroll
    for (int off = 1; off < 32; off <<= 1) {
        int y = __shfl_up_sync(0xffffffffu, x, off);
        if (lane >= off) x += y;
    }
    if (lane == 31) s_warp[wid] = x;
    __syncthreads();
    if (wid == 0) {
        int orig = (lane < 8) ? s_warp[lane] : 0;
        int s = orig;
        #pragma unroll
        for (int off = 1; off < 8; off <<= 1) {
            int y = __shfl_up_sync(0xffffffffu, s, off);
            if (lane >= off) s += y;
        }
        if (lane == 7) s_base = atomicAdd(ctr, s);
        if (lane < 8) s_warp[lane] = s - orig;
    }
    __syncthreads();
    if (i < len) {
        int excl = (x - v) + s_warp[wid] + s_base;
        base[i] = excl;
        cur[i]  = excl;
    }
}

// ---------------- scatter nnz into both CSRs ----------------
__global__ __launch_bounds__(256) void scatter_kernel(const int* __restrict__ V, const int* __restrict__ E)
{
    int i = blockIdx.x * 256 + threadIdx.x;     // NNZ exact
    int v = __ldg(&V[i]);
    int e = __ldg(&E[i]);
    int pE = atomicAdd(&g_curE[e], 1);
    g_csrE_v[pE] = v;
    int pV = atomicAdd(&g_curV[v], 1);
    g_csrV_e[pV] = e;
}

// ---------------- edge aggregation: Yv2e[e] = elu( sum w_v*Xfeat[v] / sum w_v )  -> fp16 ----------------
__global__ __launch_bounds__(256) void edge_agg_kernel()
{
    const int e = blockIdx.x * 8 + (threadIdx.x >> 5);   // 25000*8 = 200000
    const int lane = threadIdx.x & 31;
    const int base = g_baseE[e];
    const int deg  = g_zero[e];
    float4 acc = make_float4(0.f, 0.f, 0.f, 0.f);
    float denom = 0.f;
    int vcur = (deg > 0) ? __ldg(&g_csrE_v[base]) : 0;
    for (int j = 0; j < deg; j++) {
        int v = vcur;
        if (j + 1 < deg) vcur = __ldg(&g_csrE_v[base + j + 1]);   // prefetch next index
        float wv = __ldg(&g_w[v]);
        float4 xf = *(const float4*)&g_Xfeat[(size_t)v * OUTC + lane * 4];
        denom += wv;
        acc.x += wv * xf.x; acc.y += wv * xf.y; acc.z += wv * xf.z; acc.w += wv * xf.w;
    }
    float inv = (deg > 0) ? (1.f / denom) : 0.f;
    __half2 h0 = __floats2half2_rn(elu1(acc.x * inv), elu1(acc.y * inv));
    __half2 h1 = __floats2half2_rn(elu1(acc.z * inv), elu1(acc.w * inv));
    uint2 pk;
    pk.x = *reinterpret_cast<uint32_t*>(&h0);
    pk.y = *reinterpret_cast<uint32_t*>(&h1);
    *(uint2*)&g_Yv2e[(size_t)e * (OUTC/2) + lane * 2] = pk;
}

// ---------------- fused node aggregation + GEMM: out = X_init + (deg>0 ? elu(mean@Wt + bt) : 0) ----------------
#define SMROW 200
__global__ __launch_bounds__(256, 2) void node_gemm_fused_kernel(
    const float* __restrict__ S, const float* __restrict__ Wt, const float* __restrict__ bt,
    float* __restrict__ out)
{
    extern __shared__ float sm[];
    float* sM = sm;                        // 64*200
    float* sW = sm + 64 * SMROW;           // 32*132
    int*  sDeg = (int*)(sW + 32 * 132);    // 64

    const int tx = threadIdx.x;
    const int wid = tx >> 5, lane = tx & 31;
    const int n0 = blockIdx.x * 64;

    // ---- phase 1: gather means for rows wid*8 .. wid*8+7 ----
    #pragma unroll 1
    for (int m = 0; m < 8; m++) {
        int row = wid * 8 + m;
        int n = n0 + row;
        float4 accY = make_float4(0.f, 0.f, 0.f, 0.f);
        float2 accS = make_float2(0.f, 0.f);
        int deg = 0;
        if (n < N_NODES) {
            int base = g_baseV[n];
            deg = g_zero[N_EDGES + n];
            int ecur = (deg > 0) ? __ldg(&g_csrV_e[base]) : 0;
            for (int j = 0; j < deg; j++) {
                int e = ecur;
                if (j + 1 < deg) ecur = __ldg(&g_csrV_e[base + j + 1]);   // prefetch next index
                uint2 pk = *(const uint2*)&g_Yv2e[(size_t)e * (OUTC/2) + lane * 2];
                float2 f0 = __half22float2(*reinterpret_cast<__half2*>(&pk.x));
                float2 f1 = __half22float2(*reinterpret_cast<__half2*>(&pk.y));
                accY.x += f0.x; accY.y += f0.y; accY.z += f1.x; accY.w += f1.y;
                float2 s2 = *(const float2*)&S[(size_t)e * STAR_ + lane * 2];
                accS.x += s2.x; accS.y += s2.y;
            }
        }
        float inv = 1.f / fmaxf((float)deg, 1.f);
        accY.x *= inv; accY.y *= inv; accY.z *= inv; accY.w *= inv;
        accS.x *= inv; accS.y *= inv;
        *(float4*)&sM[row * SMROW + lane * 4] = accY;
        *(float2*)&sM[row * SMROW + OUTC + lane * 2] = accS;
        if (lane == 0) sDeg[row] = deg;
    }
    __syncthreads();

    // ---- phase 2: GEMM (64x128, K=192, Wt in 6 chunks of 32 rows) ----
    const int c0 = (tx & 31) * 4;
    const int r0 = (tx >> 5) * 8;

    u64 a0[8], a1[8];
    #pragma unroll
    for (int i = 0; i < 8; i++) { a0[i] = 0ull; a1[i] = 0ull; }

    #pragma unroll 1
    for (int c = 0; c < 6; c++) {
        #pragma unroll
        for (int it = 0; it < 4; it++) {
            int idx = tx + it * 256;      // 32 rows * 32 float4
            int k  = idx >> 5;
            int cq = idx & 31;
            *(float4*)&sW[k * 132 + cq * 4] = *(const float4*)&Wt[(c * 32 + k) * OUTC + cq * 4];
        }
        __syncthreads();

        #pragma unroll 4
        for (int kk = 0; kk < 32; kk++) {
            int k = c * 32 + kk;
            ulonglong2 w2 = *(ulonglong2*)&sW[kk * 132 + c0];
            #pragma unroll
            for (int i = 0; i < 8; i++) {
                u64 xx = pack2(sM[(r0 + i) * SMROW + k]);   // warp-broadcast LDS
                fma2(a0[i], xx, w2.x); fma2(a1[i], xx, w2.y);
            }
        }
        __syncthreads();
    }

    float4 bt4 = *(const float4*)&bt[c0];
    #pragma unroll
    for (int i = 0; i < 8; i++) {
        int n = n0 + r0 + i;
        if (n < N_NODES) {
            size_t oidx = (size_t)n * OUTC + c0;
            float4 o = *(const float4*)&out[oidx];           // X_init
            if (sDeg[r0 + i] > 0) {                          // isolated node -> elu(0)=0
                float2 p01 = unpack2(a0[i]), p23 = unpack2(a1[i]);
                o.x += elu1(p01.x + bt4.x);
                o.y += elu1(p01.y + bt4.y);
                o.z += elu1(p23.x + bt4.z);
                o.w += elu1(p23.y + bt4.w);
            }
            *(float4*)&out[oidx] = o;
        }
    }
}

// ---------------- launch ----------------
extern "C" void kernel_launch(void* const* d_in, const int* in_sizes, int n_in,
                              void* d_out, int out_size)
{
    const float* X  = (const float*)d_in[0];
    const int*   V  = (const int*)d_in[1];
    const int*   E  = (const int*)d_in[2];
    const float* S  = (const float*)d_in[3];
    const float* Wx = (const float*)d_in[4];
    const float* bx = (const float*)d_in[5];
    const float* Wv = (const float*)d_in[6];
    const float* bv = (const float*)d_in[7];
    const float* a  = (const float*)d_in[8];
    const float* Wt = (const float*)d_in[9];
    const float* bt = (const float*)d_in[10];
    float* out = (float*)d_out;

    void* p_zero;
    cudaGetSymbolAddress(&p_zero, g_zero);
    cudaMemsetAsync(p_zero, 0, (size_t)(N_EDGES + N_NODES + 2) * sizeof(int));

    const int smem1 = (128 * 72 + 2 * 64 * 132) * (int)sizeof(float);           // 104448
    const int smem2 = (64 * SMROW + 32 * 132) * (int)sizeof(float) + 64 * 4;    // 68352
    cudaFuncSetAttribute(gemm_x_kernel,          cudaFuncAttributeMaxDynamicSharedMemorySize, smem1);
    cudaFuncSetAttribute(node_gemm_fused_kernel, cudaFuncAttributeMaxDynamicSharedMemorySize, smem2);

    hist_kernel<<<6250, 256>>>(V, E);
    gemm_x_kernel<<<1563, 256, smem1>>>(X, Wx, bx, Wv, bv, a, out);
    alloc_kernel<<<1173, 256>>>();
    scatter_kernel<<<6250, 256>>>(V, E);
    edge_agg_kernel<<<25000, 256>>>();
    node_gemm_fused_kernel<<<1563, 256, smem2>>>(S, Wt, bt, out);
}

// round 12
// speedup vs baseline: 1.0754x; 1.0292x over previous
#include <cuda_runtime.h>
#include <cuda_fp16.h>
#include <math.h>
#include <stdint.h>

#define N_NODES 100000
#define N_EDGES 200000
#define NNZ_    1600000
#define INC 128
#define OUTC 128
#define STAR_ 64
#define KTOT 192

typedef unsigned long long u64;

// ---------------- device scratch (allocation-free) ----------------
__device__ uint32_t g_Xfeat16[(size_t)N_NODES * 64];   // 25.6 MB (fp16 X_feat rows, half2-packed)
__device__ float g_w[N_NODES];                         // exp(leaky(score)) per node
// combined fp16 message row per edge: [Yv2e (128 halves) | S (64 halves)] = 96 uint32
__device__ uint32_t g_M16[(size_t)N_EDGES * 96];       // 76.8 MB

// zero region: [histE | histV | alloc_ctr(2)]  -> single memset
__device__ int g_zero[N_EDGES + N_NODES + 2];
__device__ int g_baseE[N_EDGES];
__device__ int g_curE[N_EDGES];
__device__ int g_csrE_v[NNZ_];
__device__ int g_baseV[N_NODES];
__device__ int g_curV[N_NODES];
__device__ int g_csrV_e[NNZ_];

// ---------------- helpers ----------------
__device__ __forceinline__ float elu1(float x) {
    return x > 0.f ? x : expm1f(x);
}
// packed f32x2 FMA (Blackwell FFMA2 path via PTX)
__device__ __forceinline__ u64 pack2(float v) {
    u64 r; asm("mov.b64 %0, {%1, %1};" : "=l"(r) : "f"(v)); return r;
}
__device__ __forceinline__ void fma2(u64& d, u64 a, u64 b) {
    asm("fma.rn.f32x2 %0, %1, %2, %0;" : "+l"(d) : "l"(a), "l"(b));
}
__device__ __forceinline__ float2 unpack2(u64 v) {
    float2 r; asm("mov.b64 {%0, %1}, %2;" : "=f"(r.x), "=f"(r.y) : "l"(v)); return r;
}
__device__ __forceinline__ float2 h2f(uint32_t u) {
    return __half22float2(*reinterpret_cast<__half2*>(&u));
}
__device__ __forceinline__ uint32_t f2h(float a, float b) {
    __half2 h = __floats2half2_rn(a, b);
    return *reinterpret_cast<uint32_t*>(&h);
}

// ---------------- Kernel 1: X_init = X@Wx+bx ; X_feat(fp16) = X@Wv+bv ; w = exp(leaky(X_feat@a)) ----------------
// 64 rows x 128 cols per block; W staged in 2 k-chunks of 64 -> 102 KB smem -> 2 CTAs/SM.
__global__ __launch_bounds__(256, 2) void gemm_x_kernel(
    const float* __restrict__ X, const float* __restrict__ Wx, const float* __restrict__ bx,
    const float* __restrict__ Wv, const float* __restrict__ bv, const float* __restrict__ a_vec,
    float* __restrict__ Xinit)
{
    extern __shared__ float sm[];
    float* sXT = sm;                 // 128*72  (k-major, transposed X tile)
    float* sWx = sm + 128 * 72;      // 64*132  (one k-chunk)
    float* sWv = sWx + 64 * 132;     // 64*132

    const int tx = threadIdx.x;
    const int n0 = blockIdx.x * 64;

    #pragma unroll
    for (int it = 0; it < 8; it++) {
        int idx = tx + it * 256;
        int row = idx >> 5;
        int kq  = idx & 31;
        int n = n0 + row;
        float4 v = make_float4(0.f, 0.f, 0.f, 0.f);
        if (n < N_NODES) v = *(const float4*)&X[(size_t)n * INC + kq * 4];
        sXT[(kq * 4 + 0) * 72 + row] = v.x;
        sXT[(kq * 4 + 1) * 72 + row] = v.y;
        sXT[(kq * 4 + 2) * 72 + row] = v.z;
        sXT[(kq * 4 + 3) * 72 + row] = v.w;
    }

    const int c0 = (tx & 31) * 4;
    const int r0 = (tx >> 5) * 8;

    u64 ax0[8], ax1[8], av0[8], av1[8];
    #pragma unroll
    for (int i = 0; i < 8; i++) { ax0[i] = 0ull; ax1[i] = 0ull; av0[i] = 0ull; av1[i] = 0ull; }

    #pragma unroll
    for (int c = 0; c < 2; c++) {
        #pragma unroll
        for (int it = 0; it < 8; it++) {
            int idx = tx + it * 256;          // 64 rows * 32 float4
            int k  = idx >> 5;
            int cq = idx & 31;
            *(float4*)&sWx[k * 132 + cq * 4] = *(const float4*)&Wx[(c * 64 + k) * OUTC + cq * 4];
            *(float4*)&sWv[k * 132 + cq * 4] = *(const float4*)&Wv[(c * 64 + k) * OUTC + cq * 4];
        }
        __syncthreads();

        #pragma unroll 4
        for (int kk = 0; kk < 64; kk++) {
            int k = c * 64 + kk;
            ulonglong2 wx = *(ulonglong2*)&sWx[kk * 132 + c0];
            ulonglong2 wv = *(ulonglong2*)&sWv[kk * 132 + c0];
            float4 xa = *(float4*)&sXT[k * 72 + r0];
            float4 xb = *(float4*)&sXT[k * 72 + r0 + 4];
            float xs[8] = {xa.x, xa.y, xa.z, xa.w, xb.x, xb.y, xb.z, xb.w};
            #pragma unroll
            for (int i = 0; i < 8; i++) {
                u64 xx = pack2(xs[i]);
                fma2(ax0[i], xx, wx.x); fma2(ax1[i], xx, wx.y);
                fma2(av0[i], xx, wv.x); fma2(av1[i], xx, wv.y);
            }
        }
        __syncthreads();
    }

    float4 bx4 = *(const float4*)&bx[c0];
    float4 bv4 = *(const float4*)&bv[c0];
    float4 aa4 = *(const float4*)&a_vec[c0];
    const int lane = tx & 31;
    #pragma unroll
    for (int i = 0; i < 8; i++) {
        int n = n0 + r0 + i;
        if (n < N_NODES) {   // warp-uniform guard
            float2 x01 = unpack2(ax0[i]), x23 = unpack2(ax1[i]);
            float4 o = make_float4(x01.x + bx4.x, x01.y + bx4.y, x23.x + bx4.z, x23.y + bx4.w);
            *(float4*)&Xinit[(size_t)n * OUTC + c0] = o;
            float2 v01 = unpack2(av0[i]), v23 = unpack2(av1[i]);
            float4 f = make_float4(v01.x + bv4.x, v01.y + bv4.y, v23.x + bv4.z, v23.y + bv4.w);
            uint2 pk; pk.x = f2h(f.x, f.y); pk.y = f2h(f.z, f.w);
            *(uint2*)&g_Xfeat16[(size_t)n * 64 + lane * 2] = pk;
            float part = f.x * aa4.x + f.y * aa4.y + f.z * aa4.z + f.w * aa4.w;
            #pragma unroll
            for (int off = 16; off; off >>= 1) part += __shfl_down_sync(0xffffffffu, part, off);
            if (lane == 0) {
                float s = part > 0.f ? part : 0.2f * part;
                g_w[n] = expf(s);
            }
        }
    }
}

// ---------------- histogram: deg per edge + deg per node (into zero region) ----------------
__global__ __launch_bounds__(256) void hist_kernel(const int* __restrict__ V, const int* __restrict__ E)
{
    int i = blockIdx.x * 256 + threadIdx.x;     // 6250*256 = NNZ exact
    atomicAdd(&g_zero[__ldg(&E[i])], 1);
    atomicAdd(&g_zero[N_EDGES + __ldg(&V[i])], 1);
}

// ---------------- segment-base allocation: edges (blocks 0..781) + nodes (blocks 782..1172) ----------------
__global__ __launch_bounds__(256) void alloc_kernel()
{
    __shared__ int s_warp[8];
    __shared__ int s_base;
    const int t = threadIdx.x;
    const bool isE = blockIdx.x < 782;
    const int i = (isE ? blockIdx.x : (blockIdx.x - 782)) * 256 + t;
    const int len = isE ? N_EDGES : N_NODES;
    const int* hist = isE ? g_zero : (g_zero + N_EDGES);
    int* base = isE ? g_baseE : g_baseV;
    int* cur  = isE ? g_curE  : g_curV;
    int* ctr  = &g_zero[N_EDGES + N_NODES + (isE ? 0 : 1)];

    const int lane = t & 31, wid = t >> 5;
    int v = (i < len) ? hist[i] : 0;
    int x = v;
    #pragma unroll
    for (int off = 1; off < 32; off <<= 1) {
        int y = __shfl_up_sync(0xffffffffu, x, off);
        if (lane >= off) x += y;
    }
    if (lane == 31) s_warp[wid] = x;
    __syncthreads();
    if (wid == 0) {
        int orig = (lane < 8) ? s_warp[lane] : 0;
        int s = orig;
        #pragma unroll
        for (int off = 1; off < 8; off <<= 1) {
            int y = __shfl_up_sync(0xffffffffu, s, off);
            if (lane >= off) s += y;
        }
        if (lane == 7) s_base = atomicAdd(ctr, s);
        if (lane < 8) s_warp[lane] = s - orig;
    }
    __syncthreads();
    if (i < len) {
        int excl = (x - v) + s_warp[wid] + s_base;
        base[i] = excl;
        cur[i]  = excl;
    }
}

// ---------------- scatter nnz into both CSRs ----------------
__global__ __launch_bounds__(256) void scatter_kernel(const int* __restrict__ V, const int* __restrict__ E)
{
    int i = blockIdx.x * 256 + threadIdx.x;     // NNZ exact
    int v = __ldg(&V[i]);
    int e = __ldg(&E[i]);
    int pE = atomicAdd(&g_curE[e], 1);
    g_csrE_v[pE] = v;
    int pV = atomicAdd(&g_curV[v], 1);
    g_csrV_e[pV] = e;
}

// ---------------- edge aggregation: M16[e] = [ fp16(elu(sum w_v*Xf16[v]/sum w_v)) | fp16(S[e]) ] ----------------
__global__ __launch_bounds__(256) void edge_agg_kernel(const float* __restrict__ S)
{
    const int e = blockIdx.x * 8 + (threadIdx.x >> 5);   // 25000*8 = 200000
    const int lane = threadIdx.x & 31;
    const int base = g_baseE[e];
    const int deg  = g_zero[e];
    float4 acc = make_float4(0.f, 0.f, 0.f, 0.f);
    float denom = 0.f;
    int vcur = (deg > 0) ? __ldg(&g_csrE_v[base]) : 0;
    for (int j = 0; j < deg; j++) {
        int v = vcur;
        if (j + 1 < deg) vcur = __ldg(&g_csrE_v[base + j + 1]);   // prefetch next index
        float wv = __ldg(&g_w[v]);
        uint2 pk = *(const uint2*)&g_Xfeat16[(size_t)v * 64 + lane * 2];
        float2 f0 = h2f(pk.x), f1 = h2f(pk.y);
        denom += wv;
        acc.x += wv * f0.x; acc.y += wv * f0.y; acc.z += wv * f1.x; acc.w += wv * f1.y;
    }
    float inv = (deg > 0) ? (1.f / denom) : 0.f;
    uint2 pk;
    pk.x = f2h(elu1(acc.x * inv), elu1(acc.y * inv));
    pk.y = f2h(elu1(acc.z * inv), elu1(acc.w * inv));
    *(uint2*)&g_M16[(size_t)e * 96 + lane * 2] = pk;
    // append fp16(S[e]) — read once per edge instead of once per nnz in the node pass
    float2 s2 = *(const float2*)&S[(size_t)e * STAR_ + lane * 2];
    g_M16[(size_t)e * 96 + 64 + lane] = f2h(s2.x, s2.y);
}

// ---------------- fused node aggregation + GEMM: out = X_init + (deg>0 ? elu(mean@Wt + bt) : 0) ----------------
#define SMROW 200
__global__ __launch_bounds__(256, 2) void node_gemm_fused_kernel(
    const float* __restrict__ Wt, const float* __restrict__ bt, float* __restrict__ out)
{
    extern __shared__ float sm[];
    float* sM = sm;                        // 64*200
    float* sW = sm + 64 * SMROW;           // 32*132
    int*  sDeg = (int*)(sW + 32 * 132);    // 64

    const int tx = threadIdx.x;
    const int wid = tx >> 5, lane = tx & 31;
    const int n0 = blockIdx.x * 64;

    // ---- phase 1: gather means for rows wid*8 .. wid*8+7 (one contiguous 384B row per nnz) ----
    #pragma unroll 1
    for (int m = 0; m < 8; m++) {
        int row = wid * 8 + m;
        int n = n0 + row;
        float2 accA = make_float2(0.f, 0.f);   // cols 2l, 2l+1
        float2 accB = make_float2(0.f, 0.f);   // cols 64+2l
        float2 accS = make_float2(0.f, 0.f);   // cols 128+2l (S)
        int deg = 0;
        if (n < N_NODES) {
            int base = g_baseV[n];
            deg = g_zero[N_EDGES + n];
            int ecur = (deg > 0) ? __ldg(&g_csrV_e[base]) : 0;
            for (int j = 0; j < deg; j++) {
                int e = ecur;
                if (j + 1 < deg) ecur = __ldg(&g_csrV_e[base + j + 1]);   // prefetch next index
                const uint32_t* rowp = &g_M16[(size_t)e * 96];
                float2 f0 = h2f(__ldg(&rowp[lane]));
                float2 f1 = h2f(__ldg(&rowp[32 + lane]));
                float2 f2 = h2f(__ldg(&rowp[64 + lane]));
                accA.x += f0.x; accA.y += f0.y;
                accB.x += f1.x; accB.y += f1.y;
                accS.x += f2.x; accS.y += f2.y;
            }
        }
        float inv = 1.f / fmaxf((float)deg, 1.f);
        accA.x *= inv; accA.y *= inv;
        accB.x *= inv; accB.y *= inv;
        accS.x *= inv; accS.y *= inv;
        *(float2*)&sM[row * SMROW + 2 * lane] = accA;
        *(float2*)&sM[row * SMROW + 64 + 2 * lane] = accB;
        *(float2*)&sM[row * SMROW + 128 + 2 * lane] = accS;
        if (lane == 0) sDeg[row] = deg;
    }
    __syncthreads();

    // ---- phase 2: GEMM (64x128, K=192, Wt in 6 chunks of 32 rows) ----
    const int c0 = (tx & 31) * 4;
    const int r0 = (tx >> 5) * 8;

    u64 a0[8], a1[8];
    #pragma unroll
    for (int i = 0; i < 8; i++) { a0[i] = 0ull; a1[i] = 0ull; }

    #pragma unroll 1
    for (int c = 0; c < 6; c++) {
        #pragma unroll
        for (int it = 0; it < 4; it++) {
            int idx = tx + it * 256;      // 32 rows * 32 float4
            int k  = idx >> 5;
            int cq = idx & 31;
            *(float4*)&sW[k * 132 + cq * 4] = *(const float4*)&Wt[(c * 32 + k) * OUTC + cq * 4];
        }
        __syncthreads();

        #pragma unroll 4
        for (int kk = 0; kk < 32; kk++) {
            int k = c * 32 + kk;
            ulonglong2 w2 = *(ulonglong2*)&sW[kk * 132 + c0];
            #pragma unroll
            for (int i = 0; i < 8; i++) {
                u64 xx = pack2(sM[(r0 + i) * SMROW + k]);   // warp-broadcast LDS
                fma2(a0[i], xx, w2.x); fma2(a1[i], xx, w2.y);
            }
        }
        __syncthreads();
    }

    float4 bt4 = *(const float4*)&bt[c0];
    #pragma unroll
    for (int i = 0; i < 8; i++) {
        int n = n0 + r0 + i;
        if (n < N_NODES) {
            size_t oidx = (size_t)n * OUTC + c0;
            float4 o = *(const float4*)&out[oidx];           // X_init
            if (sDeg[r0 + i] > 0) {                          // isolated node -> elu(0)=0
                float2 p01 = unpack2(a0[i]), p23 = unpack2(a1[i]);
                o.x += elu1(p01.x + bt4.x);
                o.y += elu1(p01.y + bt4.y);
                o.z += elu1(p23.x + bt4.z);
                o.w += elu1(p23.y + bt4.w);
            }
            *(float4*)&out[oidx] = o;
        }
    }
}

// ---------------- launch ----------------
extern "C" void kernel_launch(void* const* d_in, const int* in_sizes, int n_in,
                              void* d_out, int out_size)
{
    const float* X  = (const float*)d_in[0];
    const int*   V  = (const int*)d_in[1];
    const int*   E  = (const int*)d_in[2];
    const float* S  = (const float*)d_in[3];
    const float* Wx = (const float*)d_in[4];
    const float* bx = (const float*)d_in[5];
    const float* Wv = (const float*)d_in[6];
    const float* bv = (const float*)d_in[7];
    const float* a  = (const float*)d_in[8];
    const float* Wt = (const float*)d_in[9];
    const float* bt = (const float*)d_in[10];
    float* out = (float*)d_out;

    void* p_zero;
    cudaGetSymbolAddress(&p_zero, g_zero);
    cudaMemsetAsync(p_zero, 0, (size_t)(N_EDGES + N_NODES + 2) * sizeof(int));

    const int smem1 = (128 * 72 + 2 * 64 * 132) * (int)sizeof(float);           // 104448
    const int smem2 = (64 * SMROW + 32 * 132) * (int)sizeof(float) + 64 * 4;    // 68352
    cudaFuncSetAttribute(gemm_x_kernel,          cudaFuncAttributeMaxDynamicSharedMemorySize, smem1);
    cudaFuncSetAttribute(node_gemm_fused_kernel, cudaFuncAttributeMaxDynamicSharedMemorySize, smem2);

    hist_kernel<<<6250, 256>>>(V, E);
    gemm_x_kernel<<<1563, 256, smem1>>>(X, Wx, bx, Wv, bv, a, out);
    alloc_kernel<<<1173, 256>>>();
    scatter_kernel<<<6250, 256>>>(V, E);
    edge_agg_kernel<<<25000, 256>>>(S);
    node_gemm_fused_kernel<<<1563, 256, smem2>>>(Wt, bt, out);
}

// round 13
// speedup vs baseline: 1.1025x; 1.0251x over previous
#include <cuda_runtime.h>
#include <cuda_fp16.h>
#include <math.h>
#include <stdint.h>

#define N_NODES 100000
#define N_EDGES 200000
#define NNZ_    1600000
#define INC 128
#define OUTC 128
#define STAR_ 64
#define KTOT 192

#define GX_BLOCKS 1563
#define SC_BLOCKS 6250

typedef unsigned long long u64;

// ---------------- device scratch (allocation-free) ----------------
__device__ uint32_t g_Xfeat16[(size_t)N_NODES * 64];   // 25.6 MB (fp16 X_feat rows, half2-packed)
__device__ float g_w[N_NODES];                         // exp(leaky(score)) per node
// combined fp16 message row per edge: [Yv2e (128 halves) | S (64 halves)] = 96 uint32
__device__ uint32_t g_M16[(size_t)N_EDGES * 96];       // 76.8 MB

// zero region: [histE | histV | alloc_ctr(2)]  -> single memset
__device__ int g_zero[N_EDGES + N_NODES + 2];
__device__ int g_baseE[N_EDGES];
__device__ int g_baseV[N_NODES];
__device__ int g_rankE[NNZ_];
__device__ int g_rankV[NNZ_];
__device__ int g_csrE_v[NNZ_];
__device__ int g_csrV_e[NNZ_];

// ---------------- helpers ----------------
__device__ __forceinline__ float elu1(float x) {
    return x > 0.f ? x : expm1f(x);
}
// packed f32x2 FMA (Blackwell FFMA2 path via PTX)
__device__ __forceinline__ u64 pack2(float v) {
    u64 r; asm("mov.b64 %0, {%1, %1};" : "=l"(r) : "f"(v)); return r;
}
__device__ __forceinline__ void fma2(u64& d, u64 a, u64 b) {
    asm("fma.rn.f32x2 %0, %1, %2, %0;" : "+l"(d) : "l"(a), "l"(b));
}
__device__ __forceinline__ float2 unpack2(u64 v) {
    float2 r; asm("mov.b64 {%0, %1}, %2;" : "=f"(r.x), "=f"(r.y) : "l"(v)); return r;
}
__device__ __forceinline__ float2 h2f(uint32_t u) {
    return __half22float2(*reinterpret_cast<__half2*>(&u));
}
__device__ __forceinline__ uint32_t f2h(float a, float b) {
    __half2 h = __floats2half2_rn(a, b);
    return *reinterpret_cast<uint32_t*>(&h);
}

// ---------------- histogram + rank capture ----------------
__global__ __launch_bounds__(256) void hist_kernel(const int* __restrict__ V, const int* __restrict__ E)
{
    int i = blockIdx.x * 256 + threadIdx.x;     // 6250*256 = NNZ exact
    int e = __ldg(&E[i]);
    int v = __ldg(&V[i]);
    g_rankE[i] = atomicAdd(&g_zero[e], 1);
    g_rankV[i] = atomicAdd(&g_zero[N_EDGES + v], 1);
}

// ---------------- segment-base allocation: edges (blocks 0..781) + nodes (blocks 782..1172) ----------------
__global__ __launch_bounds__(256) void alloc_kernel()
{
    __shared__ int s_warp[8];
    __shared__ int s_base;
    const int t = threadIdx.x;
    const bool isE = blockIdx.x < 782;
    const int i = (isE ? blockIdx.x : (blockIdx.x - 782)) * 256 + t;
    const int len = isE ? N_EDGES : N_NODES;
    const int* hist = isE ? g_zero : (g_zero + N_EDGES);
    int* base = isE ? g_baseE : g_baseV;
    int* ctr  = &g_zero[N_EDGES + N_NODES + (isE ? 0 : 1)];

    const int lane = t & 31, wid = t >> 5;
    int v = (i < len) ? hist[i] : 0;
    int x = v;
    #pragma unroll
    for (int off = 1; off < 32; off <<= 1) {
        int y = __shfl_up_sync(0xffffffffu, x, off);
        if (lane >= off) x += y;
    }
    if (lane == 31) s_warp[wid] = x;
    __syncthreads();
    if (wid == 0) {
        int orig = (lane < 8) ? s_warp[lane] : 0;
        int s = orig;
        #pragma unroll
        for (int off = 1; off < 8; off <<= 1) {
            int y = __shfl_up_sync(0xffffffffu, s, off);
            if (lane >= off) s += y;
        }
        if (lane == 7) s_base = atomicAdd(ctr, s);
        if (lane < 8) s_warp[lane] = s - orig;
    }
    __syncthreads();
    if (i < len) base[i] = (x - v) + s_warp[wid] + s_base;
}

// ---------------- fused: gemm_x (blocks 0..1562) || atomic-free scatter (blocks 1563..7812) ----------------
// gemm_x: X_init = X@Wx+bx ; X_feat(fp16) = X@Wv+bv ; w = exp(leaky(X_feat@a))
// 64 rows x 128 cols per block; W staged in 2 k-chunks of 64 -> 102 KB smem -> 2 CTAs/SM.
__global__ __launch_bounds__(256, 2) void gemm_scatter_kernel(
    const float* __restrict__ X, const float* __restrict__ Wx, const float* __restrict__ bx,
    const float* __restrict__ Wv, const float* __restrict__ bv, const float* __restrict__ a_vec,
    const int* __restrict__ V, const int* __restrict__ E,
    float* __restrict__ Xinit)
{
    const int tx = threadIdx.x;

    if (blockIdx.x >= GX_BLOCKS) {
        // ----- scatter branch: pure writes, no atomics -----
        int i = (blockIdx.x - GX_BLOCKS) * 256 + tx;     // NNZ exact
        int v = __ldg(&V[i]);
        int e = __ldg(&E[i]);
        g_csrE_v[__ldg(&g_baseE[e]) + g_rankE[i]] = v;
        g_csrV_e[__ldg(&g_baseV[v]) + g_rankV[i]] = e;
        return;
    }

    // ----- gemm_x branch -----
    extern __shared__ float sm[];
    float* sXT = sm;                 // 128*72  (k-major, transposed X tile)
    float* sWx = sm + 128 * 72;      // 64*132  (one k-chunk)
    float* sWv = sWx + 64 * 132;     // 64*132

    const int n0 = blockIdx.x * 64;

    #pragma unroll
    for (int it = 0; it < 8; it++) {
        int idx = tx + it * 256;
        int row = idx >> 5;
        int kq  = idx & 31;
        int n = n0 + row;
        float4 v = make_float4(0.f, 0.f, 0.f, 0.f);
        if (n < N_NODES) v = *(const float4*)&X[(size_t)n * INC + kq * 4];
        sXT[(kq * 4 + 0) * 72 + row] = v.x;
        sXT[(kq * 4 + 1) * 72 + row] = v.y;
        sXT[(kq * 4 + 2) * 72 + row] = v.z;
        sXT[(kq * 4 + 3) * 72 + row] = v.w;
    }

    const int c0 = (tx & 31) * 4;
    const int r0 = (tx >> 5) * 8;

    u64 ax0[8], ax1[8], av0[8], av1[8];
    #pragma unroll
    for (int i = 0; i < 8; i++) { ax0[i] = 0ull; ax1[i] = 0ull; av0[i] = 0ull; av1[i] = 0ull; }

    #pragma unroll
    for (int c = 0; c < 2; c++) {
        #pragma unroll
        for (int it = 0; it < 8; it++) {
            int idx = tx + it * 256;          // 64 rows * 32 float4
            int k  = idx >> 5;
            int cq = idx & 31;
            *(float4*)&sWx[k * 132 + cq * 4] = *(const float4*)&Wx[(c * 64 + k) * OUTC + cq * 4];
            *(float4*)&sWv[k * 132 + cq * 4] = *(const float4*)&Wv[(c * 64 + k) * OUTC + cq * 4];
        }
        __syncthreads();

        #pragma unroll 4
        for (int kk = 0; kk < 64; kk++) {
            int k = c * 64 + kk;
            ulonglong2 wx = *(ulonglong2*)&sWx[kk * 132 + c0];
            ulonglong2 wv = *(ulonglong2*)&sWv[kk * 132 + c0];
            float4 xa = *(float4*)&sXT[k * 72 + r0];
            float4 xb = *(float4*)&sXT[k * 72 + r0 + 4];
            float xs[8] = {xa.x, xa.y, xa.z, xa.w, xb.x, xb.y, xb.z, xb.w};
            #pragma unroll
            for (int i = 0; i < 8; i++) {
                u64 xx = pack2(xs[i]);
                fma2(ax0[i], xx, wx.x); fma2(ax1[i], xx, wx.y);
                fma2(av0[i], xx, wv.x); fma2(av1[i], xx, wv.y);
            }
        }
        __syncthreads();
    }

    float4 bx4 = *(const float4*)&bx[c0];
    float4 bv4 = *(const float4*)&bv[c0];
    float4 aa4 = *(const float4*)&a_vec[c0];
    const int lane = tx & 31;
    #pragma unroll
    for (int i = 0; i < 8; i++) {
        int n = n0 + r0 + i;
        if (n < N_NODES) {   // warp-uniform guard
            float2 x01 = unpack2(ax0[i]), x23 = unpack2(ax1[i]);
            float4 o = make_float4(x01.x + bx4.x, x01.y + bx4.y, x23.x + bx4.z, x23.y + bx4.w);
            *(float4*)&Xinit[(size_t)n * OUTC + c0] = o;
            float2 v01 = unpack2(av0[i]), v23 = unpack2(av1[i]);
            float4 f = make_float4(v01.x + bv4.x, v01.y + bv4.y, v23.x + bv4.z, v23.y + bv4.w);
            uint2 pk; pk.x = f2h(f.x, f.y); pk.y = f2h(f.z, f.w);
            *(uint2*)&g_Xfeat16[(size_t)n * 64 + lane * 2] = pk;
            float part = f.x * aa4.x + f.y * aa4.y + f.z * aa4.z + f.w * aa4.w;
            #pragma unroll
            for (int off = 16; off; off >>= 1) part += __shfl_down_sync(0xffffffffu, part, off);
            if (lane == 0) {
                float s = part > 0.f ? part : 0.2f * part;
                g_w[n] = expf(s);
            }
        }
    }
}

// ---------------- edge aggregation: M16[e] = [ fp16(elu(sum w_v*Xf16[v]/sum w_v)) | fp16(S[e]) ] ----------------
__global__ __launch_bounds__(256) void edge_agg_kernel(const float* __restrict__ S)
{
    const int e = blockIdx.x * 8 + (threadIdx.x >> 5);   // 25000*8 = 200000
    const int lane = threadIdx.x & 31;
    const int base = g_baseE[e];
    const int deg  = g_zero[e];
    float4 acc = make_float4(0.f, 0.f, 0.f, 0.f);
    float denom = 0.f;
    int vcur = (deg > 0) ? __ldg(&g_csrE_v[base]) : 0;
    for (int j = 0; j < deg; j++) {
        int v = vcur;
        if (j + 1 < deg) vcur = __ldg(&g_csrE_v[base + j + 1]);   // prefetch next index
        float wv = __ldg(&g_w[v]);
        uint2 pk = *(const uint2*)&g_Xfeat16[(size_t)v * 64 + lane * 2];
        float2 f0 = h2f(pk.x), f1 = h2f(pk.y);
        denom += wv;
        acc.x += wv * f0.x; acc.y += wv * f0.y; acc.z += wv * f1.x; acc.w += wv * f1.y;
    }
    float inv = (deg > 0) ? (1.f / denom) : 0.f;
    uint2 pk;
    pk.x = f2h(elu1(acc.x * inv), elu1(acc.y * inv));
    pk.y = f2h(elu1(acc.z * inv), elu1(acc.w * inv));
    *(uint2*)&g_M16[(size_t)e * 96 + lane * 2] = pk;
    // append fp16(S[e]) — read once per edge instead of once per nnz in the node pass
    float2 s2 = *(const float2*)&S[(size_t)e * STAR_ + lane * 2];
    g_M16[(size_t)e * 96 + 64 + lane] = f2h(s2.x, s2.y);
}

// ---------------- fused node aggregation + GEMM: out = X_init + (deg>0 ? elu(mean@Wt + bt) : 0) ----------------
#define SMROW 200
__global__ __launch_bounds__(256, 3) void node_gemm_fused_kernel(
    const float* __restrict__ Wt, const float* __restrict__ bt, float* __restrict__ out)
{
    extern __shared__ float sm[];
    float* sM = sm;                        // 64*200
    float* sW = sm + 64 * SMROW;           // 32*132
    int*  sDeg = (int*)(sW + 32 * 132);    // 64

    const int tx = threadIdx.x;
    const int wid = tx >> 5, lane = tx & 31;
    const int n0 = blockIdx.x * 64;

    // ---- phase 1: gather means for rows wid*8 .. wid*8+7 (one contiguous 384B row per nnz) ----
    #pragma unroll 1
    for (int m = 0; m < 8; m++) {
        int row = wid * 8 + m;
        int n = n0 + row;
        float2 accA = make_float2(0.f, 0.f);   // cols 2l, 2l+1
        float2 accB = make_float2(0.f, 0.f);   // cols 64+2l
        float2 accS = make_float2(0.f, 0.f);   // cols 128+2l (S)
        int deg = 0;
        if (n < N_NODES) {
            int base = g_baseV[n];
            deg = g_zero[N_EDGES + n];
            int ecur = (deg > 0) ? __ldg(&g_csrV_e[base]) : 0;
            for (int j = 0; j < deg; j++) {
                int e = ecur;
                if (j + 1 < deg) ecur = __ldg(&g_csrV_e[base + j + 1]);   // prefetch next index
                const uint32_t* rowp = &g_M16[(size_t)e * 96];
                float2 f0 = h2f(__ldg(&rowp[lane]));
                float2 f1 = h2f(__ldg(&rowp[32 + lane]));
                float2 f2 = h2f(__ldg(&rowp[64 + lane]));
                accA.x += f0.x; accA.y += f0.y;
                accB.x += f1.x; accB.y += f1.y;
                accS.x += f2.x; accS.y += f2.y;
            }
        }
        float inv = 1.f / fmaxf((float)deg, 1.f);
        accA.x *= inv; accA.y *= inv;
        accB.x *= inv; accB.y *= inv;
        accS.x *= inv; accS.y *= inv;
        *(float2*)&sM[row * SMROW + 2 * lane] = accA;
        *(float2*)&sM[row * SMROW + 64 + 2 * lane] = accB;
        *(float2*)&sM[row * SMROW + 128 + 2 * lane] = accS;
        if (lane == 0) sDeg[row] = deg;
    }
    __syncthreads();

    // ---- phase 2: GEMM (64x128, K=192, Wt in 6 chunks of 32 rows) ----
    const int c0 = (tx & 31) * 4;
    const int r0 = (tx >> 5) * 8;

    u64 a0[8], a1[8];
    #pragma unroll
    for (int i = 0; i < 8; i++) { a0[i] = 0ull; a1[i] = 0ull; }

    #pragma unroll 1
    for (int c = 0; c < 6; c++) {
        #pragma unroll
        for (int it = 0; it < 4; it++) {
            int idx = tx + it * 256;      // 32 rows * 32 float4
            int k  = idx >> 5;
            int cq = idx & 31;
            *(float4*)&sW[k * 132 + cq * 4] = *(const float4*)&Wt[(c * 32 + k) * OUTC + cq * 4];
        }
        __syncthreads();

        #pragma unroll 4
        for (int kk = 0; kk < 32; kk++) {
            int k = c * 32 + kk;
            ulonglong2 w2 = *(ulonglong2*)&sW[kk * 132 + c0];
            #pragma unroll
            for (int i = 0; i < 8; i++) {
                u64 xx = pack2(sM[(r0 + i) * SMROW + k]);   // warp-broadcast LDS
                fma2(a0[i], xx, w2.x); fma2(a1[i], xx, w2.y);
            }
        }
        __syncthreads();
    }

    float4 bt4 = *(const float4*)&bt[c0];
    #pragma unroll
    for (int i = 0; i < 8; i++) {
        int n = n0 + r0 + i;
        if (n < N_NODES) {
            size_t oidx = (size_t)n * OUTC + c0;
            float4 o = *(const float4*)&out[oidx];           // X_init
            if (sDeg[r0 + i] > 0) {                          // isolated node -> elu(0)=0
                float2 p01 = unpack2(a0[i]), p23 = unpack2(a1[i]);
                o.x += elu1(p01.x + bt4.x);
                o.y += elu1(p01.y + bt4.y);
                o.z += elu1(p23.x + bt4.z);
                o.w += elu1(p23.y + bt4.w);
            }
            *(float4*)&out[oidx] = o;
        }
    }
}

// ---------------- launch ----------------
extern "C" void kernel_launch(void* const* d_in, const int* in_sizes, int n_in,
                              void* d_out, int out_size)
{
    const float* X  = (const float*)d_in[0];
    const int*   V  = (const int*)d_in[1];
    const int*   E  = (const int*)d_in[2];
    const float* S  = (const float*)d_in[3];
    const float* Wx = (const float*)d_in[4];
    const float* bx = (const float*)d_in[5];
    const float* Wv = (const float*)d_in[6];
    const float* bv = (const float*)d_in[7];
    const float* a  = (const float*)d_in[8];
    const float* Wt = (const float*)d_in[9];
    const float* bt = (const float*)d_in[10];
    float* out = (float*)d_out;

    void* p_zero;
    cudaGetSymbolAddress(&p_zero, g_zero);
    cudaMemsetAsync(p_zero, 0, (size_t)(N_EDGES + N_NODES + 2) * sizeof(int));

    const int smem1 = (128 * 72 + 2 * 64 * 132) * (int)sizeof(float);           // 104448
    const int smem2 = (64 * SMROW + 32 * 132) * (int)sizeof(float) + 64 * 4;    // 68352
    cudaFuncSetAttribute(gemm_scatter_kernel,    cudaFuncAttributeMaxDynamicSharedMemorySize, smem1);
    cudaFuncSetAttribute(node_gemm_fused_kernel, cudaFuncAttributeMaxDynamicSharedMemorySize, smem2);

    hist_kernel<<<6250, 256>>>(V, E);
    alloc_kernel<<<1173, 256>>>();
    gemm_scatter_kernel<<<GX_BLOCKS + SC_BLOCKS, 256, smem1>>>(X, Wx, bx, Wv, bv, a, V, E, out);
    edge_agg_kernel<<<25000, 256>>>(S);
    node_gemm_fused_kernel<<<1563, 256, smem2>>>(Wt, bt, out);
}

// round 14
// speedup vs baseline: 1.1832x; 1.0732x over previous
#include <cuda_runtime.h>
#include <cuda_fp16.h>
#include <math.h>
#include <stdint.h>

#define N_NODES 100000
#define N_EDGES 200000
#define NNZ_    1600000
#define INC 128
#define OUTC 128
#define STAR_ 64
#define KTOT 192

#define GX_BLOCKS 1563
#define SC_BLOCKS 6250

typedef unsigned long long u64;

// ---------------- device scratch (allocation-free) ----------------
// packed per-node row: [X_feat fp16 (64 uint32) | w fp32-bits (1) | pad (3)]  stride 68
__device__ uint32_t g_XW16[(size_t)N_NODES * 68];      // 27.2 MB
// combined fp16 message row per edge: [Yv2e (128 halves) | S (64 halves)] = 96 uint32
__device__ uint32_t g_M16[(size_t)N_EDGES * 96];       // 76.8 MB

// zero region: [histE | histV | alloc_ctr(2)]  -> single memset
__device__ int g_zero[N_EDGES + N_NODES + 2];
__device__ int g_baseE[N_EDGES];
__device__ int g_baseV[N_NODES];
__device__ int g_rankE[NNZ_];
__device__ int g_rankV[NNZ_];
__device__ int g_csrE_v[NNZ_];
__device__ int g_csrV_e[NNZ_];

// ---------------- helpers ----------------
__device__ __forceinline__ float elu1(float x) {
    return x > 0.f ? x : expm1f(x);
}
// packed f32x2 FMA (Blackwell FFMA2 path via PTX)
__device__ __forceinline__ u64 pack2(float v) {
    u64 r; asm("mov.b64 %0, {%1, %1};" : "=l"(r) : "f"(v)); return r;
}
__device__ __forceinline__ void fma2(u64& d, u64 a, u64 b) {
    asm("fma.rn.f32x2 %0, %1, %2, %0;" : "+l"(d) : "l"(a), "l"(b));
}
__device__ __forceinline__ float2 unpack2(u64 v) {
    float2 r; asm("mov.b64 {%0, %1}, %2;" : "=f"(r.x), "=f"(r.y) : "l"(v)); return r;
}
__device__ __forceinline__ float2 h2f(uint32_t u) {
    return __half22float2(*reinterpret_cast<__half2*>(&u));
}
__device__ __forceinline__ uint32_t f2h(float a, float b) {
    __half2 h = __floats2half2_rn(a, b);
    return *reinterpret_cast<uint32_t*>(&h);
}
__device__ __forceinline__ uint32_t hadd2u(uint32_t a, uint32_t b) {
    __half2 r = __hadd2(*reinterpret_cast<const __half2*>(&a), *reinterpret_cast<const __half2*>(&b));
    return *reinterpret_cast<uint32_t*>(&r);
}

// ---------------- histogram + rank capture ----------------
__global__ __launch_bounds__(256) void hist_kernel(const int* __restrict__ V, const int* __restrict__ E)
{
    int i = blockIdx.x * 256 + threadIdx.x;     // 6250*256 = NNZ exact
    int e = __ldg(&E[i]);
    int v = __ldg(&V[i]);
    g_rankE[i] = atomicAdd(&g_zero[e], 1);
    g_rankV[i] = atomicAdd(&g_zero[N_EDGES + v], 1);
}

// ---------------- segment-base allocation: edges (blocks 0..781) + nodes (blocks 782..1172) ----------------
__global__ __launch_bounds__(256) void alloc_kernel()
{
    __shared__ int s_warp[8];
    __shared__ int s_base;
    const int t = threadIdx.x;
    const bool isE = blockIdx.x < 782;
    const int i = (isE ? blockIdx.x : (blockIdx.x - 782)) * 256 + t;
    const int len = isE ? N_EDGES : N_NODES;
    const int* hist = isE ? g_zero : (g_zero + N_EDGES);
    int* base = isE ? g_baseE : g_baseV;
    int* ctr  = &g_zero[N_EDGES + N_NODES + (isE ? 0 : 1)];

    const int lane = t & 31, wid = t >> 5;
    int v = (i < len) ? hist[i] : 0;
    int x = v;
    #pragma unroll
    for (int off = 1; off < 32; off <<= 1) {
        int y = __shfl_up_sync(0xffffffffu, x, off);
        if (lane >= off) x += y;
    }
    if (lane == 31) s_warp[wid] = x;
    __syncthreads();
    if (wid == 0) {
        int orig = (lane < 8) ? s_warp[lane] : 0;
        int s = orig;
        #pragma unroll
        for (int off = 1; off < 8; off <<= 1) {
            int y = __shfl_up_sync(0xffffffffu, s, off);
            if (lane >= off) s += y;
        }
        if (lane == 7) s_base = atomicAdd(ctr, s);
        if (lane < 8) s_warp[lane] = s - orig;
    }
    __syncthreads();
    if (i < len) base[i] = (x - v) + s_warp[wid] + s_base;
}

// ---------------- fused: gemm_x (blocks 0..1562) || atomic-free scatter (blocks 1563..7812) ----------------
__global__ __launch_bounds__(256, 2) void gemm_scatter_kernel(
    const float* __restrict__ X, const float* __restrict__ Wx, const float* __restrict__ bx,
    const float* __restrict__ Wv, const float* __restrict__ bv, const float* __restrict__ a_vec,
    const int* __restrict__ V, const int* __restrict__ E,
    float* __restrict__ Xinit)
{
    const int tx = threadIdx.x;

    if (blockIdx.x >= GX_BLOCKS) {
        // ----- scatter branch: pure writes, no atomics -----
        int i = (blockIdx.x - GX_BLOCKS) * 256 + tx;     // NNZ exact
        int v = __ldg(&V[i]);
        int e = __ldg(&E[i]);
        g_csrE_v[__ldg(&g_baseE[e]) + g_rankE[i]] = v;
        g_csrV_e[__ldg(&g_baseV[v]) + g_rankV[i]] = e;
        return;
    }

    // ----- gemm_x branch -----
    extern __shared__ float sm[];
    float* sXT = sm;                 // 128*72  (k-major, transposed X tile)
    float* sWx = sm + 128 * 72;      // 64*132  (one k-chunk)
    float* sWv = sWx + 64 * 132;     // 64*132

    const int n0 = blockIdx.x * 64;

    #pragma unroll
    for (int it = 0; it < 8; it++) {
        int idx = tx + it * 256;
        int row = idx >> 5;
        int kq  = idx & 31;
        int n = n0 + row;
        float4 v = make_float4(0.f, 0.f, 0.f, 0.f);
        if (n < N_NODES) v = *(const float4*)&X[(size_t)n * INC + kq * 4];
        sXT[(kq * 4 + 0) * 72 + row] = v.x;
        sXT[(kq * 4 + 1) * 72 + row] = v.y;
        sXT[(kq * 4 + 2) * 72 + row] = v.z;
        sXT[(kq * 4 + 3) * 72 + row] = v.w;
    }

    const int c0 = (tx & 31) * 4;
    const int r0 = (tx >> 5) * 8;

    u64 ax0[8], ax1[8], av0[8], av1[8];
    #pragma unroll
    for (int i = 0; i < 8; i++) { ax0[i] = 0ull; ax1[i] = 0ull; av0[i] = 0ull; av1[i] = 0ull; }

    #pragma unroll
    for (int c = 0; c < 2; c++) {
        #pragma unroll
        for (int it = 0; it < 8; it++) {
            int idx = tx + it * 256;          // 64 rows * 32 float4
            int k  = idx >> 5;
            int cq = idx & 31;
            *(float4*)&sWx[k * 132 + cq * 4] = *(const float4*)&Wx[(c * 64 + k) * OUTC + cq * 4];
            *(float4*)&sWv[k * 132 + cq * 4] = *(const float4*)&Wv[(c * 64 + k) * OUTC + cq * 4];
        }
        __syncthreads();

        #pragma unroll 4
        for (int kk = 0; kk < 64; kk++) {
            int k = c * 64 + kk;
            ulonglong2 wx = *(ulonglong2*)&sWx[kk * 132 + c0];
            ulonglong2 wv = *(ulonglong2*)&sWv[kk * 132 + c0];
            float4 xa = *(float4*)&sXT[k * 72 + r0];
            float4 xb = *(float4*)&sXT[k * 72 + r0 + 4];
            float xs[8] = {xa.x, xa.y, xa.z, xa.w, xb.x, xb.y, xb.z, xb.w};
            #pragma unroll
            for (int i = 0; i < 8; i++) {
                u64 xx = pack2(xs[i]);
                fma2(ax0[i], xx, wx.x); fma2(ax1[i], xx, wx.y);
                fma2(av0[i], xx, wv.x); fma2(av1[i], xx, wv.y);
            }
        }
        __syncthreads();
    }

    float4 bx4 = *(const float4*)&bx[c0];
    float4 bv4 = *(const float4*)&bv[c0];
    float4 aa4 = *(const float4*)&a_vec[c0];
    const int lane = tx & 31;
    #pragma unroll
    for (int i = 0; i < 8; i++) {
        int n = n0 + r0 + i;
        if (n < N_NODES) {   // warp-uniform guard
            float2 x01 = unpack2(ax0[i]), x23 = unpack2(ax1[i]);
            float4 o = make_float4(x01.x + bx4.x, x01.y + bx4.y, x23.x + bx4.z, x23.y + bx4.w);
            *(float4*)&Xinit[(size_t)n * OUTC + c0] = o;
            float2 v01 = unpack2(av0[i]), v23 = unpack2(av1[i]);
            float4 f = make_float4(v01.x + bv4.x, v01.y + bv4.y, v23.x + bv4.z, v23.y + bv4.w);
            uint2 pk; pk.x = f2h(f.x, f.y); pk.y = f2h(f.z, f.w);
            *(uint2*)&g_XW16[(size_t)n * 68 + lane * 2] = pk;
            float part = f.x * aa4.x + f.y * aa4.y + f.z * aa4.z + f.w * aa4.w;
            #pragma unroll
            for (int off = 16; off; off >>= 1) part += __shfl_down_sync(0xffffffffu, part, off);
            if (lane == 0) {
                float s = part > 0.f ? part : 0.2f * part;
                g_XW16[(size_t)n * 68 + 64] = __float_as_uint(expf(s));
            }
        }
    }
}

// ---------------- edge aggregation: M16[e] = [ fp16(elu(sum w_v*Xf16[v]/sum w_v)) | fp16(S[e]) ] ----------------
__global__ __launch_bounds__(256) void edge_agg_kernel(const float* __restrict__ S)
{
    const int e = blockIdx.x * 8 + (threadIdx.x >> 5);   // 25000*8 = 200000
    const int lane = threadIdx.x & 31;
    const int base = g_baseE[e];
    const int deg  = g_zero[e];
    float4 acc = make_float4(0.f, 0.f, 0.f, 0.f);
    float denom = 0.f;
    #pragma unroll 2
    for (int j = 0; j < deg; j++) {
        int v = __ldg(&g_csrE_v[base + j]);              // warp-broadcast
        const uint32_t* rowp = &g_XW16[(size_t)v * 68];  // one base: payload [R], w [R+256]
        uint2 pk = *(const uint2*)&rowp[lane * 2];
        float wv = __uint_as_float(__ldg(&rowp[64]));
        float2 f0 = h2f(pk.x), f1 = h2f(pk.y);
        denom += wv;
        acc.x += wv * f0.x; acc.y += wv * f0.y; acc.z += wv * f1.x; acc.w += wv * f1.y;
    }
    float inv = (deg > 0) ? (1.f / denom) : 0.f;
    uint2 pk;
    pk.x = f2h(elu1(acc.x * inv), elu1(acc.y * inv));
    pk.y = f2h(elu1(acc.z * inv), elu1(acc.w * inv));
    *(uint2*)&g_M16[(size_t)e * 96 + lane * 2] = pk;
    // append fp16(S[e]) — read once per edge instead of once per nnz in the node pass
    float2 s2 = *(const float2*)&S[(size_t)e * STAR_ + lane * 2];
    g_M16[(size_t)e * 96 + 64 + lane] = f2h(s2.x, s2.y);
}

// ---------------- fused node aggregation + GEMM: out = X_init + (deg>0 ? elu(mean@Wt + bt) : 0) ----------------
#define SMROW 200
__global__ __launch_bounds__(256, 3) void node_gemm_fused_kernel(
    const float* __restrict__ Wt, const float* __restrict__ bt, float* __restrict__ out)
{
    extern __shared__ float sm[];
    float* sM = sm;                        // 64*200
    float* sW = sm + 64 * SMROW;           // 32*132
    int*  sDeg = (int*)(sW + 32 * 132);    // 64

    const int tx = threadIdx.x;
    const int wid = tx >> 5, lane = tx & 31;
    const int n0 = blockIdx.x * 64;

    // ---- phase 1: gather means, pairwise-fp16 reduction (HADD2 pairs, fp32 accumulate) ----
    #pragma unroll 1
    for (int m = 0; m < 8; m++) {
        int row = wid * 8 + m;
        int n = n0 + row;
        float2 accA = make_float2(0.f, 0.f);
        float2 accB = make_float2(0.f, 0.f);
        float2 accS = make_float2(0.f, 0.f);
        int deg = 0;
        if (n < N_NODES) {
            int base = g_baseV[n];
            deg = g_zero[N_EDGES + n];
            int j = 0;
            for (; j + 1 < deg; j += 2) {
                int e0 = __ldg(&g_csrV_e[base + j]);
                int e1 = __ldg(&g_csrV_e[base + j + 1]);
                const uint32_t* r0 = &g_M16[(size_t)e0 * 96];
                const uint32_t* r1 = &g_M16[(size_t)e1 * 96];
                uint32_t a0 = __ldg(&r0[lane]),      b0 = __ldg(&r1[lane]);
                uint32_t a1 = __ldg(&r0[32 + lane]), b1 = __ldg(&r1[32 + lane]);
                uint32_t a2 = __ldg(&r0[64 + lane]), b2 = __ldg(&r1[64 + lane]);
                float2 pA = h2f(hadd2u(a0, b0));
                float2 pB = h2f(hadd2u(a1, b1));
                float2 pS = h2f(hadd2u(a2, b2));
                accA.x += pA.x; accA.y += pA.y;
                accB.x += pB.x; accB.y += pB.y;
                accS.x += pS.x; accS.y += pS.y;
            }
            if (j < deg) {   // odd tail in fp32
                int e0 = __ldg(&g_csrV_e[base + j]);
                const uint32_t* r0 = &g_M16[(size_t)e0 * 96];
                float2 f0 = h2f(__ldg(&r0[lane]));
                float2 f1 = h2f(__ldg(&r0[32 + lane]));
                float2 f2 = h2f(__ldg(&r0[64 + lane]));
                accA.x += f0.x; accA.y += f0.y;
                accB.x += f1.x; accB.y += f1.y;
                accS.x += f2.x; accS.y += f2.y;
            }
        }
        float inv = 1.f / fmaxf((float)deg, 1.f);
        accA.x *= inv; accA.y *= inv;
        accB.x *= inv; accB.y *= inv;
        accS.x *= inv; accS.y *= inv;
        *(float2*)&sM[row * SMROW + 2 * lane] = accA;
        *(float2*)&sM[row * SMROW + 64 + 2 * lane] = accB;
        *(float2*)&sM[row * SMROW + 128 + 2 * lane] = accS;
        if (lane == 0) sDeg[row] = deg;
    }
    __syncthreads();

    // ---- phase 2: GEMM (64x128, K=192, Wt in 6 chunks of 32 rows) ----
    const int c0 = (tx & 31) * 4;
    const int r0 = (tx >> 5) * 8;

    u64 a0[8], a1[8];
    #pragma unroll
    for (int i = 0; i < 8; i++) { a0[i] = 0ull; a1[i] = 0ull; }

    #pragma unroll 1
    for (int c = 0; c < 6; c++) {
        #pragma unroll
        for (int it = 0; it < 4; it++) {
            int idx = tx + it * 256;      // 32 rows * 32 float4
            int k  = idx >> 5;
            int cq = idx & 31;
            *(float4*)&sW[k * 132 + cq * 4] = *(const float4*)&Wt[(c * 32 + k) * OUTC + cq * 4];
        }
        __syncthreads();

        #pragma unroll 4
        for (int kk = 0; kk < 32; kk++) {
            int k = c * 32 + kk;
            ulonglong2 w2 = *(ulonglong2*)&sW[kk * 132 + c0];
            #pragma unroll
            for (int i = 0; i < 8; i++) {
                u64 xx = pack2(sM[(r0 + i) * SMROW + k]);   // warp-broadcast LDS
                fma2(a0[i], xx, w2.x); fma2(a1[i], xx, w2.y);
            }
        }
        __syncthreads();
    }

    float4 bt4 = *(const float4*)&bt[c0];
    #pragma unroll
    for (int i = 0; i < 8; i++) {
        int n = n0 + r0 + i;
        if (n < N_NODES) {
            size_t oidx = (size_t)n * OUTC + c0;
            float4 o = *(const float4*)&out[oidx];           // X_init
            if (sDeg[r0 + i] > 0) {                          // isolated node -> elu(0)=0
                float2 p01 = unpack2(a0[i]), p23 = unpack2(a1[i]);
                o.x += elu1(p01.x + bt4.x);
                o.y += elu1(p01.y + bt4.y);
                o.z += elu1(p23.x + bt4.z);
                o.w += elu1(p23.y + bt4.w);
            }
            *(float4*)&out[oidx] = o;
        }
    }
}

// ---------------- launch ----------------
extern "C" void kernel_launch(void* const* d_in, const int* in_sizes, int n_in,
                              void* d_out, int out_size)
{
    const float* X  = (const float*)d_in[0];
    const int*   V  = (const int*)d_in[1];
    const int*   E  = (const int*)d_in[2];
    const float* S  = (const float*)d_in[3];
    const float* Wx = (const float*)d_in[4];
    const float* bx = (const float*)d_in[5];
    const float* Wv = (const float*)d_in[6];
    const float* bv = (const float*)d_in[7];
    const float* a  = (const float*)d_in[8];
    const float* Wt = (const float*)d_in[9];
    const float* bt = (const float*)d_in[10];
    float* out = (float*)d_out;

    void* p_zero;
    cudaGetSymbolAddress(&p_zero, g_zero);
    cudaMemsetAsync(p_zero, 0, (size_t)(N_EDGES + N_NODES + 2) * sizeof(int));

    const int smem1 = (128 * 72 + 2 * 64 * 132) * (int)sizeof(float);           // 104448
    const int smem2 = (64 * SMROW + 32 * 132) * (int)sizeof(float) + 64 * 4;    // 68352
    cudaFuncSetAttribute(gemm_scatter_kernel,    cudaFuncAttributeMaxDynamicSharedMemorySize, smem1);
    cudaFuncSetAttribute(node_gemm_fused_kernel, cudaFuncAttributeMaxDynamicSharedMemorySize, smem2);

    hist_kernel<<<6250, 256>>>(V, E);
    alloc_kernel<<<1173, 256>>>();
    gemm_scatter_kernel<<<GX_BLOCKS + SC_BLOCKS, 256, smem1>>>(X, Wx, bx, Wv, bv, a, V, E, out);
    edge_agg_kernel<<<25000, 256>>>(S);
    node_gemm_fused_kernel<<<1563, 256, smem2>>>(Wt, bt, out);
}